// round 4
// baseline (speedup 1.0000x reference)
#include <cuda_runtime.h>
#include <stdint.h>

#define D_MODEL 4096
#define RANK 32
#define THREADS 256
#define COLS 4                      // columns per thread
#define DCHUNK (THREADS * COLS)     // 1024 columns per CTA
#define TBATCH 8                    // tokens staged per smem batch

typedef unsigned long long ull;

// Packed dual-FMA: d.{lo,hi} += a.{lo,hi} * b.{lo,hi}  (Blackwell f32x2 pipe)
__device__ __forceinline__ void fma2(ull& d, ull a, ull b) {
    asm("fma.rn.f32x2 %0, %1, %2, %0;" : "+l"(d) : "l"(a), "l"(b));
}
__device__ __forceinline__ float lo32(ull v) { return __uint_as_float((unsigned)v); }
__device__ __forceinline__ float hi32(ull v) { return __uint_as_float((unsigned)(v >> 32)); }

// Probe whether the widened base table is float32 (else int32).
// int8-valued int32s: positive -> exponent field 0x00, negative -> 0xFF.
// float32 of magnitude 1..127: exponent in normal range.
__device__ __forceinline__ bool probe_wq_is_float(const unsigned* w) {
    #pragma unroll
    for (int i = 0; i < 16; ++i) {
        unsigned u = __ldg(w + i);
        if (u == 0u) continue;
        unsigned e = (u >> 23) & 0xFFu;
        return (e != 0u && e != 0xFFu);
    }
    return false;
}

template<bool ISF>
__device__ __forceinline__ void emb_main(
    const int* __restrict__ ids, const int* __restrict__ wq, float scale,
    const float* __restrict__ A, const float* __restrict__ Bm,
    float* __restrict__ out, int ntok, int gy, int by, int tx,
    ull (*sA)[TBATCH][RANK])
{
    const int col0 = blockIdx.x * DCHUNK + tx * COLS;

    // Register-resident B columns, packed as f32x2 pairs (reused by every token)
    ull b01[RANK], b23[RANK];
    #pragma unroll
    for (int r = 0; r < RANK; ++r) {
        const ulonglong2 bv =
            *reinterpret_cast<const ulonglong2*>(Bm + (size_t)r * D_MODEL + col0);
        b01[r] = bv.x;
        b23[r] = bv.y;
    }

    const int tpb  = (ntok + gy - 1) / gy;
    const int t0   = by * tpb;
    const int tend = min(t0 + tpb, ntok);
    if (t0 >= tend) return;  // uniform per CTA

    const int stok  = tx >> 5;   // staging token slot (0..7)
    const int srank = tx & 31;   // staging rank

    // Stage batch 0 (SCALING = ALPHA/RANK = 0.5 folded in; exact pow2)
    {
        int t = t0 + stok;
        if (t < tend) {
            int id = __ldg(ids + t);
            unsigned u = __float_as_uint(__ldg(A + (size_t)id * RANK + srank) * 0.5f);
            sA[0][stok][srank] = ((ull)u << 32) | (ull)u;
        }
    }
    __syncthreads();

    // Rolling prefetch of this thread's 4-element base-row slice (16B LDG)
    int4 qpref = *reinterpret_cast<const int4*>(
        wq + (size_t)__ldg(ids + t0) * D_MODEL + col0);

    int buf = 0;
    for (int bb = t0; bb < tend; bb += TBATCH) {
        // Stage NEXT batch into the other buffer (LDG latency overlaps compute)
        {
            int t = bb + TBATCH + stok;
            if (t < tend) {
                int id = __ldg(ids + t);
                unsigned u = __float_as_uint(__ldg(A + (size_t)id * RANK + srank) * 0.5f);
                sA[buf ^ 1][stok][srank] = ((ull)u << 32) | (ull)u;
            }
        }

        const int blim = min(bb + TBATCH, tend);
        for (int t = bb; t < blim; ++t) {
            int4 q = qpref;
            if (t + 1 < tend) {
                int idn = __ldg(ids + t + 1);
                qpref = *reinterpret_cast<const int4*>(
                    wq + (size_t)idn * D_MODEL + col0);
            }

            ull acc01 = 0ULL, acc23 = 0ULL;
            const ull* a = sA[buf][t - bb];
            #pragma unroll
            for (int r = 0; r < RANK; ++r) {
                ull ap = a[r];            // broadcast LDS.64 {a[r],a[r]} (pre-scaled)
                fma2(acc01, ap, b01[r]);
                fma2(acc23, ap, b23[r]);
            }

            float bx, by2, bz, bw;
            if (ISF) {
                bx = __int_as_float(q.x); by2 = __int_as_float(q.y);
                bz = __int_as_float(q.z); bw  = __int_as_float(q.w);
            } else {
                bx = (float)q.x; by2 = (float)q.y;
                bz = (float)q.z; bw  = (float)q.w;
            }
            float4 o;
            o.x = fmaf(bx,  scale, lo32(acc01));
            o.y = fmaf(by2, scale, hi32(acc01));
            o.z = fmaf(bz,  scale, lo32(acc23));
            o.w = fmaf(bw,  scale, hi32(acc23));
            *reinterpret_cast<float4*>(out + (size_t)t * D_MODEL + col0) = o;
        }
        __syncthreads();
        buf ^= 1;
    }
}

__global__ void __launch_bounds__(THREADS, 1)
emb_lora_kernel(const int* __restrict__ ids,
                const int* __restrict__ wq,
                const float* __restrict__ wscale,
                const float* __restrict__ A,
                const float* __restrict__ Bm,
                float* __restrict__ out,
                int ntok)
{
    __shared__ ull sA[2][TBATCH][RANK];
    const float scale = wscale[0];
    const bool isf = probe_wq_is_float((const unsigned*)wq);
    if (isf)
        emb_main<true >(ids, wq, scale, A, Bm, out, ntok,
                        gridDim.y, blockIdx.y, threadIdx.x, sA);
    else
        emb_main<false>(ids, wq, scale, A, Bm, out, ntok,
                        gridDim.y, blockIdx.y, threadIdx.x, sA);
}

extern "C" void kernel_launch(void* const* d_in, const int* in_sizes, int n_in,
                              void* d_out, int out_size) {
    // Bind inputs by UNIQUE element counts — robust to metadata ordering.
    //   ids: ntok | w_base_q: VOCAB*D_MODEL (largest) | w_scale: 1
    //   adapter_A: VOCAB*RANK | adapter_B: RANK*D_MODEL
    const int*   ids    = nullptr;
    const int*   wq     = nullptr;
    const float* wscale = nullptr;
    const float* A      = nullptr;
    const float* Bm     = nullptr;

    long long ntok_ll = (long long)out_size / D_MODEL;
    long long wq_sz = 0;
    int wq_idx = -1;
    for (int i = 0; i < n_in; ++i)
        if ((long long)in_sizes[i] > wq_sz) { wq_sz = in_sizes[i]; wq_idx = i; }
    wq = (const int*)d_in[wq_idx];

    for (int i = 0; i < n_in; ++i) {
        if (i == wq_idx) continue;
        long long s = in_sizes[i];
        if (s == 1)                              wscale = (const float*)d_in[i];
        else if (s == ntok_ll)                   ids    = (const int*)d_in[i];
        else if (s == (long long)RANK * D_MODEL) Bm     = (const float*)d_in[i];
        else                                     A      = (const float*)d_in[i];
    }

    const int ntok = (int)ntok_ll;       // 16384 tokens

    dim3 grid(D_MODEL / DCHUNK, 148);    // (4 column-chunks, 148 token blocks)
    emb_lora_kernel<<<grid, THREADS>>>(ids, wq, wscale, A, Bm, (float*)d_out, ntok);
}

// round 5
// speedup vs baseline: 1.1185x; 1.1185x over previous
#include <cuda_runtime.h>
#include <stdint.h>

#define D_MODEL 4096
#define RANK 32
#define THREADS 256
#define COLS 2                      // columns per thread
#define DCHUNK (THREADS * COLS)     // 512 columns per CTA
#define TBATCH 8                    // tokens staged per smem batch
#define PREF 4                      // prefetch pipeline depth (MLP)

typedef unsigned long long ull;

// Packed dual-FMA: d.{lo,hi} += a.{lo,hi} * b.{lo,hi}  (Blackwell f32x2 pipe)
__device__ __forceinline__ void fma2(ull& d, ull a, ull b) {
    asm("fma.rn.f32x2 %0, %1, %2, %0;" : "+l"(d) : "l"(a), "l"(b));
}
__device__ __forceinline__ void add2(ull& d, ull a) {
    asm("add.rn.f32x2 %0, %0, %1;" : "+l"(d) : "l"(a));
}
__device__ __forceinline__ float lo32(ull v) { return __uint_as_float((unsigned)v); }
__device__ __forceinline__ float hi32(ull v) { return __uint_as_float((unsigned)(v >> 32)); }

// Probe whether the widened base table is float32 (else int32).
__device__ __forceinline__ bool probe_wq_is_float(const unsigned* w) {
    #pragma unroll
    for (int i = 0; i < 16; ++i) {
        unsigned u = __ldg(w + i);
        if (u == 0u) continue;
        unsigned e = (u >> 23) & 0xFFu;
        return (e != 0u && e != 0xFFu);
    }
    return false;
}

template<bool ISF>
__device__ __forceinline__ void emb_main(
    const int* __restrict__ ids, const int* __restrict__ wq, float scale,
    const float* __restrict__ A, const float* __restrict__ Bm,
    float* __restrict__ out, int ntok, int gy, int by, int tx,
    ull (*sA)[TBATCH][RANK])
{
    const int col0 = blockIdx.x * DCHUNK + tx * COLS;

    // Register-resident B columns as f32x2 pairs (64 regs, reused every token)
    ull b01[RANK];
    #pragma unroll
    for (int r = 0; r < RANK; ++r)
        b01[r] = *reinterpret_cast<const ull*>(Bm + (size_t)r * D_MODEL + col0);

    const int tpb  = (ntok + gy - 1) / gy;
    const int t0   = by * tpb;
    const int tend = min(t0 + tpb, ntok);
    if (t0 >= tend) return;  // uniform per CTA

    const int stok  = tx >> 5;   // staging token slot (0..7)
    const int srank = tx & 31;   // staging rank

    // Stage batch 0 of a-vectors (SCALING = 0.5 folded in; exact pow2)
    {
        int t = t0 + stok;
        if (t < tend) {
            int id = __ldg(ids + t);
            unsigned u = __float_as_uint(__ldg(A + (size_t)id * RANK + srank) * 0.5f);
            sA[0][stok][srank] = ((ull)u << 32) | (ull)u;
        }
    }
    __syncthreads();

    // Prime a 4-deep prefetch pipeline of base-row slices (8B LDG each)
    int2 qp[PREF];
    #pragma unroll
    for (int i = 0; i < PREF; ++i) {
        int t = t0 + i;
        if (t < tend)
            qp[i] = *reinterpret_cast<const int2*>(
                wq + (size_t)__ldg(ids + t) * D_MODEL + col0);
    }

    int buf = 0;
    for (int bb = t0; bb < tend; bb += TBATCH) {
        // Stage NEXT batch of a-vectors into the other buffer
        {
            int t = bb + TBATCH + stok;
            if (t < tend) {
                int id = __ldg(ids + t);
                unsigned u = __float_as_uint(__ldg(A + (size_t)id * RANK + srank) * 0.5f);
                sA[buf ^ 1][stok][srank] = ((ull)u << 32) | (ull)u;
            }
        }

        const int blim = min(bb + TBATCH, tend);
        for (int t = bb; t < blim; ++t) {
            const int slot = (t - t0) & (PREF - 1);
            int2 q = qp[slot];
            // Refill this pipeline slot PREF tokens ahead
            if (t + PREF < tend) {
                int idn = __ldg(ids + t + PREF);
                qp[slot] = *reinterpret_cast<const int2*>(
                    wq + (size_t)idn * D_MODEL + col0);
            }

            // Two half-depth accumulator chains (even/odd ranks)
            ull accA = 0ULL, accB = 0ULL;
            const ull* a = sA[buf][t - bb];
            #pragma unroll
            for (int r = 0; r < RANK; r += 2) {
                fma2(accA, a[r],     b01[r]);
                fma2(accB, a[r + 1], b01[r + 1]);
            }
            add2(accA, accB);

            float bx, byv;
            if (ISF) { bx = __int_as_float(q.x); byv = __int_as_float(q.y); }
            else     { bx = (float)q.x;          byv = (float)q.y; }

            float2 o;
            o.x = fmaf(bx,  scale, lo32(accA));
            o.y = fmaf(byv, scale, hi32(accA));
            *reinterpret_cast<float2*>(out + (size_t)t * D_MODEL + col0) = o;
        }
        __syncthreads();
        buf ^= 1;
    }
}

__global__ void __launch_bounds__(THREADS, 2)
emb_lora_kernel(const int* __restrict__ ids,
                const int* __restrict__ wq,
                const float* __restrict__ wscale,
                const float* __restrict__ A,
                const float* __restrict__ Bm,
                float* __restrict__ out,
                int ntok)
{
    __shared__ ull sA[2][TBATCH][RANK];
    const float scale = wscale[0];
    const bool isf = probe_wq_is_float((const unsigned*)wq);
    if (isf)
        emb_main<true >(ids, wq, scale, A, Bm, out, ntok,
                        gridDim.y, blockIdx.y, threadIdx.x, sA);
    else
        emb_main<false>(ids, wq, scale, A, Bm, out, ntok,
                        gridDim.y, blockIdx.y, threadIdx.x, sA);
}

extern "C" void kernel_launch(void* const* d_in, const int* in_sizes, int n_in,
                              void* d_out, int out_size) {
    // Bind inputs by UNIQUE element counts — robust to metadata ordering.
    const int*   ids    = nullptr;
    const int*   wq     = nullptr;
    const float* wscale = nullptr;
    const float* A      = nullptr;
    const float* Bm     = nullptr;

    long long ntok_ll = (long long)out_size / D_MODEL;
    long long wq_sz = 0;
    int wq_idx = -1;
    for (int i = 0; i < n_in; ++i)
        if ((long long)in_sizes[i] > wq_sz) { wq_sz = in_sizes[i]; wq_idx = i; }
    wq = (const int*)d_in[wq_idx];

    for (int i = 0; i < n_in; ++i) {
        if (i == wq_idx) continue;
        long long s = in_sizes[i];
        if (s == 1)                              wscale = (const float*)d_in[i];
        else if (s == ntok_ll)                   ids    = (const int*)d_in[i];
        else if (s == (long long)RANK * D_MODEL) Bm     = (const float*)d_in[i];
        else                                     A      = (const float*)d_in[i];
    }

    const int ntok = (int)ntok_ll;       // 16384 tokens

    dim3 grid(D_MODEL / DCHUNK, 148);    // (8 column-chunks, 148 token blocks)
    emb_lora_kernel<<<grid, THREADS>>>(ids, wq, wscale, A, Bm, (float*)d_out, ntok);
}

// round 7
// speedup vs baseline: 2.9080x; 2.5999x over previous
#include <cuda_runtime.h>
#include <cuda_bf16.h>
#include <stdint.h>

#define D_MODEL 4096
#define RANK    32
#define TOKT    128          // tokens per CTA tile
#define COLT    128          // columns per CTA tile
#define THREADS 256
#define SA      80           // bytes per sA row: 32 bf16 + 8 pad
#define SB      80           // bytes per sB row: 32 bf16 + 8 pad
#define SL      136          // bytes per sLora row: 64 bf16 + 4 pad

#define OFF_IDS  16
#define OFF_A    1024                    // 128*80  = 10240
#define OFF_B    (OFF_A + TOKT * SA)     // 11264, 128*80 = 10240
#define OFF_LORA (OFF_B + COLT * SB)     // 21504, 128*136 = 17408
#define SM_TOTAL (OFF_LORA + TOKT * SL)  // 38912 < 48KB static limit

__device__ __forceinline__ unsigned h2u(__nv_bfloat162 h) {
    return *reinterpret_cast<unsigned*>(&h);
}

// HMMA bf16: D(16x8,f32) += A(16x16) * B(16x8)  — sm_80+, legal on compute_103
__device__ __forceinline__ void mma16816(float& d0, float& d1, float& d2, float& d3,
                                         unsigned a0, unsigned a1, unsigned a2, unsigned a3,
                                         unsigned b0, unsigned b1) {
    asm volatile("mma.sync.aligned.m16n8k16.row.col.f32.bf16.bf16.f32 "
                 "{%0,%1,%2,%3}, {%4,%5,%6,%7}, {%8,%9}, {%0,%1,%2,%3};"
                 : "+f"(d0), "+f"(d1), "+f"(d2), "+f"(d3)
                 : "r"(a0), "r"(a1), "r"(a2), "r"(a3), "r"(b0), "r"(b1));
}

__global__ void __launch_bounds__(THREADS)
emb_lora_mma(const int* __restrict__ ids, const int* __restrict__ wq,
             const float* __restrict__ wscale, const float* __restrict__ A,
             const float* __restrict__ Bm, float* __restrict__ out, int ntok)
{
    __shared__ __align__(16) unsigned char sm[SM_TOTAL];

    const int tid  = threadIdx.x;
    const int wid  = tid >> 5;
    const int lane = tid & 31;
    const int g    = lane >> 2;       // mma groupID (0..7)
    const int tig  = lane & 3;        // thread-in-group
    const int t0   = blockIdx.y * TOKT;
    const int col0 = blockIdx.x * COLT;
    int* sIds = (int*)(sm + OFF_IDS);

    // ids cache
    if (tid < TOKT) {
        int t = t0 + tid;
        sIds[tid] = (t < ntok) ? __ldg(ids + t) : 0;
    }

    // dtype probe: widened base table float32 vs int32 (uniform across threads)
    int isf = 0;
    #pragma unroll
    for (int i = 0; i < 16; ++i) {
        unsigned u = __ldg((const unsigned*)wq + i);
        if (u == 0u) continue;
        unsigned e = (u >> 23) & 0xFFu;
        isf = (e != 0u && e != 0xFFu);
        break;
    }
    __syncthreads();

    // ---- build bf16 A-tile [tok][k], SCALING=0.5 folded (exact pow2) ----
    #pragma unroll
    for (int i = 0; i < 8; ++i) {
        int p  = tid + i * THREADS;          // 0..2047
        int tl = p >> 4, kp = p & 15;        // token, k-pair
        int id = sIds[tl];
        float2 v = *reinterpret_cast<const float2*>(A + (size_t)id * RANK + 2 * kp);
        *reinterpret_cast<unsigned*>(sm + OFF_A + tl * SA + kp * 4) =
            h2u(__floats2bfloat162_rn(v.x * 0.5f, v.y * 0.5f));
    }
    // ---- build bf16 B-tile [n][k] (transpose of Bm[k][n]) ----
    #pragma unroll
    for (int i = 0; i < 8; ++i) {
        int p  = tid + i * THREADS;
        int n  = p & 127, kp = p >> 7;       // n fastest -> coalesced global reads
        const float* bp = Bm + (size_t)(2 * kp) * D_MODEL + col0 + n;
        *reinterpret_cast<unsigned*>(sm + OFF_B + n * SB + kp * 4) =
            h2u(__floats2bfloat162_rn(__ldg(bp), __ldg(bp + D_MODEL)));
    }
    __syncthreads();

    // ---- A fragments for this warp's 16 token rows (held all kernel) ----
    const int tb = wid * 16;
    const unsigned char* ar = sm + OFF_A + (tb + g) * SA + tig * 4;
    const unsigned a0l = *(const unsigned*)(ar);
    const unsigned a1l = *(const unsigned*)(ar + 8 * SA);
    const unsigned a2l = *(const unsigned*)(ar + 16);
    const unsigned a3l = *(const unsigned*)(ar + 8 * SA + 16);
    const unsigned a0h = *(const unsigned*)(ar + 32);
    const unsigned a1h = *(const unsigned*)(ar + 8 * SA + 32);
    const unsigned a2h = *(const unsigned*)(ar + 48);
    const unsigned a3h = *(const unsigned*)(ar + 8 * SA + 48);

    const float scale = __ldg(wscale);

    #pragma unroll
    for (int c = 0; c < 2; ++c) {      // two 64-col passes
        // ---- compute 8 n-blocks, store lora (bf16) to sLora ----
        #pragma unroll
        for (int nb = 0; nb < 8; ++nb) {
            const unsigned char* bb = sm + OFF_B + (c * 64 + nb * 8 + g) * SB + tig * 4;
            unsigned b0l = *(const unsigned*)(bb);
            unsigned b1l = *(const unsigned*)(bb + 16);
            unsigned b0h = *(const unsigned*)(bb + 32);
            unsigned b1h = *(const unsigned*)(bb + 48);
            float d0 = 0.f, d1 = 0.f, d2 = 0.f, d3 = 0.f;
            mma16816(d0, d1, d2, d3, a0l, a1l, a2l, a3l, b0l, b1l);
            mma16816(d0, d1, d2, d3, a0h, a1h, a2h, a3h, b0h, b1h);
            int colp = nb * 8 + 2 * tig;   // col within pass (0..63)
            *reinterpret_cast<unsigned*>(sm + OFF_LORA + (tb + g) * SL + colp * 2) =
                h2u(__floats2bfloat162_rn(d0, d1));
            *reinterpret_cast<unsigned*>(sm + OFF_LORA + (tb + g + 8) * SL + colp * 2) =
                h2u(__floats2bfloat162_rn(d2, d3));
        }
        __syncthreads();

        // ---- fused epilogue: coalesced gather + add + store, 64 cols ----
        const int colb = col0 + 64 * c;
        #pragma unroll 4
        for (int j = 0; j < 16; ++j) {
            int tl = tb + j;
            int t  = t0 + tl;
            if (t < ntok) {
                int id = sIds[tl];
                int2 q = __ldg(reinterpret_cast<const int2*>(
                             wq + (size_t)id * D_MODEL + colb) + lane);
                unsigned lvu = *reinterpret_cast<const unsigned*>(
                    sm + OFF_LORA + tl * SL + lane * 4);
                __nv_bfloat162 lv = *reinterpret_cast<__nv_bfloat162*>(&lvu);
                float bx = isf ? __int_as_float(q.x) : (float)q.x;
                float by = isf ? __int_as_float(q.y) : (float)q.y;
                float2 o = make_float2(fmaf(bx, scale, __bfloat162float(lv.x)),
                                       fmaf(by, scale, __bfloat162float(lv.y)));
                *reinterpret_cast<float2*>(
                    out + (size_t)t * D_MODEL + colb + lane * 2) = o;
            }
        }
        __syncthreads();   // protect sLora before next pass overwrites
    }
}

extern "C" void kernel_launch(void* const* d_in, const int* in_sizes, int n_in,
                              void* d_out, int out_size) {
    // Bind inputs by UNIQUE element counts (robust to metadata ordering).
    const int*   ids    = nullptr;
    const int*   wq     = nullptr;
    const float* wscale = nullptr;
    const float* A      = nullptr;
    const float* Bm     = nullptr;

    long long ntok_ll = (long long)out_size / D_MODEL;
    long long wq_sz = 0;
    int wq_idx = -1;
    for (int i = 0; i < n_in; ++i)
        if ((long long)in_sizes[i] > wq_sz) { wq_sz = in_sizes[i]; wq_idx = i; }
    wq = (const int*)d_in[wq_idx];

    for (int i = 0; i < n_in; ++i) {
        if (i == wq_idx) continue;
        long long s = in_sizes[i];
        if (s == 1)                              wscale = (const float*)d_in[i];
        else if (s == ntok_ll)                   ids    = (const int*)d_in[i];
        else if (s == (long long)RANK * D_MODEL) Bm     = (const float*)d_in[i];
        else                                     A      = (const float*)d_in[i];
    }

    const int ntok = (int)ntok_ll;                        // 16384
    dim3 grid(D_MODEL / COLT, (ntok + TOKT - 1) / TOKT);  // (32, 128)
    emb_lora_mma<<<grid, THREADS>>>(ids, wq, wscale, A, Bm, (float*)d_out, ntok);
}